// round 7
// baseline (speedup 1.0000x reference)
#include <cuda_runtime.h>
#include <cstdint>

// Batched occupancy-grid ray marching.
// Inputs (metadata order):
//   d_in[0] occ_grid  : bool [4,128,128,128], 8388608 elems — marshalled dtype
//                       UNKNOWN (uint8/int32/float32/bf16); auto-detected.
//   d_in[1] rays_o    : f32  [32768,3]
//   d_in[2] rays_d    : f32  [32768,3]
//   d_in[3] rays_bidx : i32  [32768]
//   d_in[4] max_steps : i32 scalar
// Output (flat f32): pts [N,S,3] ++ t [N,S] ++ mask [N,S] (0/1)

#define RES 128
#define STEP_SIZE 0.005f
#define TPB 128

// occ element width mode: 0=uint8, 1=int32, 2=float32, 3=16-bit
__device__ int g_occ_mode;

__global__ void detect_occ_mode(const uint32_t* __restrict__ occ_w, int n_elems)
{
    // Sample 64 words, strided over the SMALLEST possible buffer
    // (n_elems bytes = n_elems/4 words) so reads are in-bounds for any dtype.
    __shared__ int sh_f32, sh_bf16, sh_not01;
    const int tid = threadIdx.x;
    if (tid == 0) { sh_f32 = 0; sh_bf16 = 0; sh_not01 = 0; }
    __syncthreads();

    const int nwords = n_elems / 4;
    const int stride = nwords / 64;
    const uint32_t w = occ_w[(size_t)tid * stride];

    if (w == 0x3F803F80u) atomicOr(&sh_bf16, 1);
    if (w == 0x3F800000u) atomicOr(&sh_f32, 1);
    if (w > 1u)           atomicOr(&sh_not01, 1);
    __syncthreads();

    if (tid == 0) {
        int mode;
        if (sh_bf16)        mode = 3;   // bf16 pairs (1.0,1.0)
        else if (sh_f32)    mode = 2;   // float32 1.0f
        else if (!sh_not01) mode = 1;   // every word is 0/1 -> int32
        else                mode = 0;   // byte patterns -> uint8
        g_occ_mode = mode;
    }
}

__device__ __forceinline__ bool occ_at(const void* __restrict__ occ, long idx, int mode)
{
    switch (mode) {
        case 0:  return ((const uint8_t*) occ)[idx] != 0;
        case 1:  return ((const int*)     occ)[idx] != 0;
        case 2:  return ((const float*)   occ)[idx] != 0.0f;
        default: return ((const uint16_t*)occ)[idx] != 0;  // bf16: 0x0000 == 0.0
    }
}

__device__ __forceinline__ int clamp_idx(float v) {
    // matches: clip(int32(v), 0, RES-1); trunc-toward-zero == C cast
    int i = (int)v;
    i = i < 0 ? 0 : i;
    i = i > (RES - 1) ? (RES - 1) : i;
    return i;
}

__device__ __forceinline__ float safe_inv(float d) {
    const float eps = 1e-10f;
    float sd = (fabsf(d) < eps) ? ((d >= 0.0f) ? eps : -eps) : d;
    return 1.0f / sd;
}

struct Sample { float px, py, pz, t, m; };

__device__ __forceinline__ Sample eval_sample(
    int s, float nearv, float tmax, bool valid,
    float ox, float oy, float oz, float dx, float dy, float dz,
    const void* __restrict__ occ, long grid_base, int mode)
{
    // explicit mul-then-add: bitwise match to reference's near + (s+0.5)*h
    const float t = __fadd_rn(nearv, __fmul_rn((float)s + 0.5f, STEP_SIZE));

    const float px = __fadd_rn(ox, __fmul_rn(t, dx));
    const float py = __fadd_rn(oy, __fmul_rn(t, dy));
    const float pz = __fadd_rn(oz, __fmul_rn(t, dz));

    const bool in_box = valid && (t < tmax);

    bool m = false;
    if (in_box) {
        const float fx = __fmul_rn(__fadd_rn(__fmul_rn(px, 0.5f), 0.5f), (float)RES);
        const float fy = __fmul_rn(__fadd_rn(__fmul_rn(py, 0.5f), 0.5f), (float)RES);
        const float fz = __fmul_rn(__fadd_rn(__fmul_rn(pz, 0.5f), 0.5f), (float)RES);
        const int gx = clamp_idx(fx);
        const int gy = clamp_idx(fy);
        const int gz = clamp_idx(fz);
        m = occ_at(occ, grid_base + ((long)gx * RES + gy) * RES + gz, mode);
    }

    Sample r;
    const float fm = m ? 1.0f : 0.0f;
    r.px = m ? px : 0.0f;
    r.py = m ? py : 0.0f;
    r.pz = m ? pz : 0.0f;
    r.t  = t;
    r.m  = fm;
    return r;
}

__global__ void __launch_bounds__(TPB, 8)
raymarch_kernel(const void*  __restrict__ occ,
                const float* __restrict__ rays_o,
                const float* __restrict__ rays_d,
                const int*   __restrict__ rays_bidx,
                float* __restrict__ out_pts,
                float* __restrict__ out_t,
                float* __restrict__ out_mask,
                int S)
{
    const int ray = blockIdx.x;
    const int tid = threadIdx.x;
    const int mode = g_occ_mode;   // uniform across grid

    // Ray setup (redundant per thread; broadcast loads hit L1)
    const float ox = rays_o[ray * 3 + 0];
    const float oy = rays_o[ray * 3 + 1];
    const float oz = rays_o[ray * 3 + 2];
    const float dx = rays_d[ray * 3 + 0];
    const float dy = rays_d[ray * 3 + 1];
    const float dz = rays_d[ray * 3 + 2];

    const float ix = safe_inv(dx);
    const float iy = safe_inv(dy);
    const float iz = safe_inv(dz);

    const float t0x = (-1.0f - ox) * ix, t1x = (1.0f - ox) * ix;
    const float t0y = (-1.0f - oy) * iy, t1y = (1.0f - oy) * iy;
    const float t0z = (-1.0f - oz) * iz, t1z = (1.0f - oz) * iz;

    const float tmin = fmaxf(fmaxf(fminf(t0x, t1x), fminf(t0y, t1y)), fminf(t0z, t1z));
    const float tmax = fminf(fminf(fmaxf(t0x, t1x), fmaxf(t0y, t1y)), fmaxf(t0z, t1z));
    const float nearv = fmaxf(tmin, 0.0f);
    const bool  valid = (tmax > nearv);

    const long grid_base = (long)rays_bidx[ray] * (RES * RES * RES);

    float* pts_row  = out_pts  + (size_t)ray * S * 3;
    float* t_row    = out_t    + (size_t)ray * S;
    float* m_row    = out_mask + (size_t)ray * S;

    const int S4 = S & ~3;  // full 4-step chunks

    // Fast path: each thread handles 4 consecutive steps, float4 stores.
    // For S=512 this loop runs exactly once per thread (s0 = tid*4).
    for (int s0 = tid * 4; s0 < S4; s0 += TPB * 4) {
        Sample a = eval_sample(s0 + 0, nearv, tmax, valid, ox, oy, oz, dx, dy, dz, occ, grid_base, mode);
        Sample b = eval_sample(s0 + 1, nearv, tmax, valid, ox, oy, oz, dx, dy, dz, occ, grid_base, mode);
        Sample c = eval_sample(s0 + 2, nearv, tmax, valid, ox, oy, oz, dx, dy, dz, occ, grid_base, mode);
        Sample d = eval_sample(s0 + 3, nearv, tmax, valid, ox, oy, oz, dx, dy, dz, occ, grid_base, mode);

        float4* dp = (float4*)(pts_row + (size_t)s0 * 3);
        dp[0] = make_float4(a.px, a.py, a.pz, b.px);
        dp[1] = make_float4(b.py, b.pz, c.px, c.py);
        dp[2] = make_float4(c.pz, d.px, d.py, d.pz);

        *(float4*)(t_row + s0) = make_float4(a.t, b.t, c.t, d.t);
        *(float4*)(m_row + s0) = make_float4(a.m, b.m, c.m, d.m);
    }

    // Ragged tail (never taken for S=512)
    for (int s = S4 + tid; s < S; s += TPB) {
        Sample a = eval_sample(s, nearv, tmax, valid, ox, oy, oz, dx, dy, dz, occ, grid_base, mode);
        pts_row[(size_t)s * 3 + 0] = a.px;
        pts_row[(size_t)s * 3 + 1] = a.py;
        pts_row[(size_t)s * 3 + 2] = a.pz;
        t_row[s] = a.t;
        m_row[s] = a.m;
    }
}

extern "C" void kernel_launch(void* const* d_in, const int* in_sizes, int n_in,
                              void* d_out, int out_size)
{
    const void*  occ       = d_in[0];
    const float* rays_o    = (const float*)d_in[1];
    const float* rays_d    = (const float*)d_in[2];
    const int*   rays_bidx = (const int*)d_in[3];

    const int N = in_sizes[1] / 3;                        // 32768
    const int S = (int)((long)out_size / ((long)N * 5));  // 512

    float* out_pts  = (float*)d_out;
    float* out_t    = out_pts + (size_t)N * S * 3;
    float* out_mask = out_t   + (size_t)N * S;

    detect_occ_mode<<<1, 64>>>((const uint32_t*)occ, in_sizes[0]);
    raymarch_kernel<<<N, TPB>>>(occ, rays_o, rays_d, rays_bidx,
                                out_pts, out_t, out_mask, S);
}

// round 11
// speedup vs baseline: 1.1243x; 1.1243x over previous
#include <cuda_runtime.h>
#include <cstdint>

// Batched occupancy-grid ray marching.
//   d_in[0] occ_grid  : bool [4,128,128,128], 8388608 elems — dtype auto-detected
//   d_in[1] rays_o    : f32  [32768,3]
//   d_in[2] rays_d    : f32  [32768,3]
//   d_in[3] rays_bidx : i32  [32768]
//   d_in[4] max_steps : i32
// Output (flat f32): pts [N,S,3] ++ t [N,S] ++ mask [N,S]

#define RES 128
#define STEP_SIZE 0.005f
#define TPB 128

// occ element mode: 0=uint8, 1=int32, 2=float32, 3=bf16
__device__ int g_occ_mode;

__global__ void detect_occ_mode(const uint32_t* __restrict__ occ_w, int n_elems)
{
    __shared__ int sh_f32, sh_bf16, sh_not01;
    const int tid = threadIdx.x;
    if (tid == 0) { sh_f32 = 0; sh_bf16 = 0; sh_not01 = 0; }
    __syncthreads();

    // sample within the smallest possible buffer (n_elems bytes)
    const int nwords = n_elems / 4;
    const int stride = nwords / 64;
    const uint32_t w = occ_w[(size_t)tid * stride];

    if (w == 0x3F803F80u) atomicOr(&sh_bf16, 1);
    if (w == 0x3F800000u) atomicOr(&sh_f32, 1);
    if (w > 1u)           atomicOr(&sh_not01, 1);
    __syncthreads();

    if (tid == 0) {
        int mode;
        if (sh_bf16)        mode = 3;
        else if (sh_f32)    mode = 2;
        else if (!sh_not01) mode = 1;
        else                mode = 0;
        g_occ_mode = mode;
    }
}

__device__ __forceinline__ int clamp_idx(float v) {
    int i = (int)v;                      // trunc == reference int32 cast
    i = i < 0 ? 0 : i;
    i = i > (RES - 1) ? (RES - 1) : i;
    return i;
}

__device__ __forceinline__ float safe_inv(float d) {
    const float eps = 1e-10f;
    float sd = (fabsf(d) < eps) ? ((d >= 0.0f) ? eps : -eps) : d;
    return 1.0f / sd;
}

__global__ void __launch_bounds__(TPB, 12)
raymarch_kernel(const uint8_t* __restrict__ occ8,
                const float* __restrict__ rays_o,
                const float* __restrict__ rays_d,
                const int*   __restrict__ rays_bidx,
                float* __restrict__ out_pts,
                float* __restrict__ out_t,
                float* __restrict__ out_mask,
                int S)
{
    const int ray = blockIdx.x;
    const int tid = threadIdx.x;

    // one byte per element tells truthiness, at (idx << shift) + off:
    //   u8:(0,0)  i32:(2,0)  f32:(2,3)  bf16:(1,1)
    const int mode  = g_occ_mode;
    const int shift = (mode == 0) ? 0 : (mode == 3) ? 1 : 2;
    const int boff  = (mode == 2) ? 3 : (mode == 3) ? 1 : 0;

    const float ox = rays_o[ray * 3 + 0];
    const float oy = rays_o[ray * 3 + 1];
    const float oz = rays_o[ray * 3 + 2];
    const float dx = rays_d[ray * 3 + 0];
    const float dy = rays_d[ray * 3 + 1];
    const float dz = rays_d[ray * 3 + 2];

    const float ix = safe_inv(dx);
    const float iy = safe_inv(dy);
    const float iz = safe_inv(dz);

    const float t0x = (-1.0f - ox) * ix, t1x = (1.0f - ox) * ix;
    const float t0y = (-1.0f - oy) * iy, t1y = (1.0f - oy) * iy;
    const float t0z = (-1.0f - oz) * iz, t1z = (1.0f - oz) * iz;

    const float tmin = fmaxf(fmaxf(fminf(t0x, t1x), fminf(t0y, t1y)), fminf(t0z, t1z));
    const float tmax = fminf(fminf(fmaxf(t0x, t1x), fmaxf(t0y, t1y)), fmaxf(t0z, t1z));
    const float nearv = fmaxf(tmin, 0.0f);
    const bool  valid = (tmax > nearv);

    const long grid_base = (long)rays_bidx[ray] * (RES * RES * RES);
    const uint8_t* __restrict__ gbase = occ8 + ((grid_base << shift) + boff);

    float* pts_row = out_pts  + (size_t)ray * S * 3;
    float* t_row   = out_t    + (size_t)ray * S;
    float* m_row   = out_mask + (size_t)ray * S;

    const int S4 = S & ~3;

    for (int s0 = tid * 4; s0 < S4; s0 += TPB * 4) {
        float tv[4], pxv[4], pyv[4], pzv[4];
        bool  inb[4];
        long  adr[4];

        #pragma unroll
        for (int i = 0; i < 4; i++) {
            const int s = s0 + i;
            // mul-then-add everywhere: bitwise match to reference
            const float t = __fadd_rn(nearv, __fmul_rn((float)s + 0.5f, STEP_SIZE));
            const float px = __fadd_rn(ox, __fmul_rn(t, dx));
            const float py = __fadd_rn(oy, __fmul_rn(t, dy));
            const float pz = __fadd_rn(oz, __fmul_rn(t, dz));

            const float fx = __fmul_rn(__fadd_rn(__fmul_rn(px, 0.5f), 0.5f), (float)RES);
            const float fy = __fmul_rn(__fadd_rn(__fmul_rn(py, 0.5f), 0.5f), (float)RES);
            const float fz = __fmul_rn(__fadd_rn(__fmul_rn(pz, 0.5f), 0.5f), (float)RES);
            const long lin = ((long)clamp_idx(fx) * RES + clamp_idx(fy)) * RES + clamp_idx(fz);

            tv[i] = t; pxv[i] = px; pyv[i] = py; pzv[i] = pz;
            inb[i] = valid && (t < tmax);
            adr[i] = lin << shift;
        }

        // batched unconditional gathers (MLP=4); clamped idx is always in-bounds
        uint8_t ob[4];
        #pragma unroll
        for (int i = 0; i < 4; i++) ob[i] = __ldg(gbase + adr[i]);

        float pm[4];
        #pragma unroll
        for (int i = 0; i < 4; i++) {
            const bool m = inb[i] && (ob[i] != 0);
            pm[i] = m ? 1.0f : 0.0f;
            pxv[i] = m ? pxv[i] : 0.0f;
            pyv[i] = m ? pyv[i] : 0.0f;
            pzv[i] = m ? pzv[i] : 0.0f;
        }

        float4* dp = (float4*)(pts_row + (size_t)s0 * 3);
        dp[0] = make_float4(pxv[0], pyv[0], pzv[0], pxv[1]);
        dp[1] = make_float4(pyv[1], pzv[1], pxv[2], pyv[2]);
        dp[2] = make_float4(pzv[2], pxv[3], pyv[3], pzv[3]);

        *(float4*)(t_row + s0) = make_float4(tv[0], tv[1], tv[2], tv[3]);
        *(float4*)(m_row + s0) = make_float4(pm[0], pm[1], pm[2], pm[3]);
    }

    // ragged tail (never taken for S=512)
    for (int s = S4 + tid; s < S; s += TPB) {
        const float t = __fadd_rn(nearv, __fmul_rn((float)s + 0.5f, STEP_SIZE));
        const float px = __fadd_rn(ox, __fmul_rn(t, dx));
        const float py = __fadd_rn(oy, __fmul_rn(t, dy));
        const float pz = __fadd_rn(oz, __fmul_rn(t, dz));
        const float fx = __fmul_rn(__fadd_rn(__fmul_rn(px, 0.5f), 0.5f), (float)RES);
        const float fy = __fmul_rn(__fadd_rn(__fmul_rn(py, 0.5f), 0.5f), (float)RES);
        const float fz = __fmul_rn(__fadd_rn(__fmul_rn(pz, 0.5f), 0.5f), (float)RES);
        const long lin = ((long)clamp_idx(fx) * RES + clamp_idx(fy)) * RES + clamp_idx(fz);
        const bool m = valid && (t < tmax) && (__ldg(gbase + (lin << shift)) != 0);
        pts_row[(size_t)s * 3 + 0] = m ? px : 0.0f;
        pts_row[(size_t)s * 3 + 1] = m ? py : 0.0f;
        pts_row[(size_t)s * 3 + 2] = m ? pz : 0.0f;
        t_row[s] = t;
        m_row[s] = m ? 1.0f : 0.0f;
    }
}

extern "C" void kernel_launch(void* const* d_in, const int* in_sizes, int n_in,
                              void* d_out, int out_size)
{
    const uint8_t* occ       = (const uint8_t*)d_in[0];
    const float*   rays_o    = (const float*)d_in[1];
    const float*   rays_d    = (const float*)d_in[2];
    const int*     rays_bidx = (const int*)d_in[3];

    const int N = in_sizes[1] / 3;                        // 32768
    const int S = (int)((long)out_size / ((long)N * 5));  // 512

    float* out_pts  = (float*)d_out;
    float* out_t    = out_pts + (size_t)N * S * 3;
    float* out_mask = out_t   + (size_t)N * S;

    detect_occ_mode<<<1, 64>>>((const uint32_t*)d_in[0], in_sizes[0]);
    raymarch_kernel<<<N, TPB>>>(occ, rays_o, rays_d, rays_bidx,
                                out_pts, out_t, out_mask, S);
}